// round 15
// baseline (speedup 1.0000x reference)
#include <cuda_runtime.h>
#include <cuda_bf16.h>
#include <math.h>

#define D      512
#define KNN    20
#define MAXN   100000
#define MAXCH  256
#define CHUNK  512        // values per stage-A warp
#define RPL    16         // regs per lane (CHUNK/32)
#define FINF   3.0e38f

// ---------------- persistent scratch ----------------
__device__ float g_tn2[MAXN];
__device__ float g_score[MAXN];
__device__ float g_sq[KNN * MAXN];
__device__ float g_cand_d[KNN * MAXCH * KNN];
__device__ int   g_cand_i[KNN * MAXCH * KNN];
__device__ float g_nb[KNN * D];
__device__ float g_pxk[KNN];
__device__ float g_sqnn[KNN * KNN];
__device__ unsigned g_nbh[32 * (D / 2)];   // bf16x2 neighbors, rows 20..31 zero
__device__ unsigned g_rowdone[KNN];        // per-row stage-A counters (self-reset)
__device__ unsigned g_done;                // row-finisher counter (self-reset)

#define CVTB(res, lo, hi) \
    asm("cvt.rn.bf16x2.f32 %0, %1, %2;" : "=r"(res) : "f"(hi), "f"(lo))

// ---------------- pass 1 ----------------
__global__ void k_pass1(const float* __restrict__ X, const float* __restrict__ T, int n) {
    int w    = blockIdx.x * (blockDim.x >> 5) + (threadIdx.x >> 5);
    int lane = threadIdx.x & 31;
    if (w >= n) return;
    const float4* row = (const float4*)(T + (size_t)w * D);
    const float4* xv  = (const float4*)X;
    float tn2 = 0.f, dx = 0.f;
#pragma unroll
    for (int i = 0; i < 4; i++) {
        float4 t = row[lane + 32 * i];
        float4 x = __ldg(&xv[lane + 32 * i]);
        tn2 += t.x * t.x + t.y * t.y + t.z * t.z + t.w * t.w;
        dx  += t.x * x.x + t.y * x.y + t.z * x.z + t.w * x.w;
    }
#pragma unroll
    for (int o = 16; o; o >>= 1) {
        tn2 += __shfl_xor_sync(0xffffffffu, tn2, o);
        dx  += __shfl_xor_sync(0xffffffffu, dx, o);
    }
    if (lane == 0) { g_tn2[w] = tn2; g_score[w] = tn2 - 2.f * dx; }
}

// ---------------- fused top-k ----------------
// grid = (ceil(nch/8), rows), 256 threads. Stage A: warp w owns chunk blockIdx.x*8+w.
// Last block per row: stage-B merge + epilogue. mode 0: gather; mode 1: sqnn + final.
__global__ void k_topk(int mode, int n, int nch, const float* __restrict__ X,
                       const float* __restrict__ T, float* out) {
    int row = blockIdx.y;
    int tid = threadIdx.x, lane = tid & 31, w = tid >> 5;
    int c = blockIdx.x * 8 + w;
    int nbx = gridDim.x;
    __shared__ float s_cv[8 * KNN];
    __shared__ int   s_ci[8 * KNN];
    __shared__ int   s_fi[KNN];
    __shared__ int   s_last;

    // ---- stage A: tournament top-20 of this warp's 512-chunk ----
    if (c < nch) {
        const float* v = mode ? (g_sq + (size_t)row * n) : g_score;
        int base = c * CHUNK;
        float val[RPL];
#pragma unroll
        for (int r = 0; r < RPL; r++) {
            int g = base + lane + 32 * r;
            val[r] = (g < n) ? v[g] : FINF;
        }
        float* od = g_cand_d + ((size_t)row * MAXCH + c) * KNN;
        int*   oi = g_cand_i + ((size_t)row * MAXCH + c) * KNN;
        int ibase = base + lane;
        for (int it = 0; it < KNN; it++) {
            // tournament min (value, reg-idx); strict < keeps lowest reg idx on ties
            float t8[8]; int i8[8];
#pragma unroll
            for (int i = 0; i < 8; i++) {
                bool cc = val[2 * i + 1] < val[2 * i];
                t8[i] = cc ? val[2 * i + 1] : val[2 * i];
                i8[i] = cc ? (2 * i + 1) : (2 * i);
            }
            float t4[4]; int i4[4];
#pragma unroll
            for (int i = 0; i < 4; i++) {
                bool cc = t8[2 * i + 1] < t8[2 * i];
                t4[i] = cc ? t8[2 * i + 1] : t8[2 * i];
                i4[i] = cc ? i8[2 * i + 1] : i8[2 * i];
            }
            float t2[2]; int i2t[2];
#pragma unroll
            for (int i = 0; i < 2; i++) {
                bool cc = t4[2 * i + 1] < t4[2 * i];
                t2[i] = cc ? t4[2 * i + 1] : t4[2 * i];
                i2t[i] = cc ? i4[2 * i + 1] : i4[2 * i];
            }
            bool cc = t2[1] < t2[0];
            float bv = cc ? t2[1] : t2[0];
            int   br = cc ? i2t[1] : i2t[0];
            int bi = (bv >= FINF) ? 0x7fffffff : (ibase + (br << 5));
#pragma unroll
            for (int o = 16; o; o >>= 1) {
                float ov = __shfl_xor_sync(0xffffffffu, bv, o);
                int   oj = __shfl_xor_sync(0xffffffffu, bi, o);
                if (ov < bv || (ov == bv && oj < bi)) { bv = ov; bi = oj; }
            }
            int rel = bi - ibase;
#pragma unroll
            for (int r = 0; r < RPL; r++)
                if (rel == (r << 5)) val[r] = FINF;
            if (lane == 0) { od[it] = bv; oi[it] = bi; }
        }
    }

    // ---- last block per row proceeds to stage B ----
    __threadfence();
    __syncthreads();
    if (tid == 0) s_last = (atomicAdd(&g_rowdone[row], 1u) == (unsigned)(nbx - 1)) ? 1 : 0;
    __syncthreads();
    if (!s_last) return;
    if (tid == 0) g_rowdone[row] = 0;

    int m = nch * KNN;                    // up to 3920 candidates
    const float* cd = g_cand_d + (size_t)row * MAXCH * KNN;
    const int*   ci = g_cand_i + (size_t)row * MAXCH * KNN;

    // phase 1: warp w covers candidate slots [w*512, w*512+512)
    float val[RPL]; int idx[RPL];
#pragma unroll
    for (int r = 0; r < RPL; r++) {
        int j = w * 512 + lane + 32 * r;
        bool ok = j < m;
        val[r] = ok ? cd[j] : FINF;
        idx[r] = ok ? ci[j] : 0x7fffffff;
    }
    for (int it = 0; it < KNN; it++) {
        float t8[8]; int x8[8];
#pragma unroll
        for (int i = 0; i < 8; i++) {
            bool cc = (val[2 * i + 1] < val[2 * i]) ||
                      (val[2 * i + 1] == val[2 * i] && idx[2 * i + 1] < idx[2 * i]);
            t8[i] = cc ? val[2 * i + 1] : val[2 * i];
            x8[i] = cc ? idx[2 * i + 1] : idx[2 * i];
        }
        float t4[4]; int x4[4];
#pragma unroll
        for (int i = 0; i < 4; i++) {
            bool cc = (t8[2 * i + 1] < t8[2 * i]) ||
                      (t8[2 * i + 1] == t8[2 * i] && x8[2 * i + 1] < x8[2 * i]);
            t4[i] = cc ? t8[2 * i + 1] : t8[2 * i];
            x4[i] = cc ? x8[2 * i + 1] : x8[2 * i];
        }
        float t2[2]; int x2[2];
#pragma unroll
        for (int i = 0; i < 2; i++) {
            bool cc = (t4[2 * i + 1] < t4[2 * i]) ||
                      (t4[2 * i + 1] == t4[2 * i] && x4[2 * i + 1] < x4[2 * i]);
            t2[i] = cc ? t4[2 * i + 1] : t4[2 * i];
            x2[i] = cc ? x4[2 * i + 1] : x4[2 * i];
        }
        bool cc = (t2[1] < t2[0]) || (t2[1] == t2[0] && x2[1] < x2[0]);
        float bv = cc ? t2[1] : t2[0];
        int   bi = cc ? x2[1] : x2[0];
#pragma unroll
        for (int o = 16; o; o >>= 1) {
            float ov = __shfl_xor_sync(0xffffffffu, bv, o);
            int   oj = __shfl_xor_sync(0xffffffffu, bi, o);
            if (ov < bv || (ov == bv && oj < bi)) { bv = ov; bi = oj; }
        }
#pragma unroll
        for (int r = 0; r < RPL; r++)
            if (idx[r] == bi) val[r] = FINF;
        if (lane == 0) { s_cv[w * KNN + it] = bv; s_ci[w * KNN + it] = bi; }
    }
    __syncthreads();

    // phase 2: warp 0 merges 160 candidates
    if (w == 0) {
        float v2[5]; int i2[5];
#pragma unroll
        for (int r = 0; r < 5; r++) { int j = lane + 32 * r; v2[r] = s_cv[j]; i2[r] = s_ci[j]; }
        for (int it = 0; it < KNN; it++) {
            float bv = v2[0]; int bi = i2[0];
#pragma unroll
            for (int r = 1; r < 5; r++)
                if (v2[r] < bv || (v2[r] == bv && i2[r] < bi)) { bv = v2[r]; bi = i2[r]; }
#pragma unroll
            for (int o = 16; o; o >>= 1) {
                float ov = __shfl_xor_sync(0xffffffffu, bv, o);
                int   oj = __shfl_xor_sync(0xffffffffu, bi, o);
                if (ov < bv || (ov == bv && oj < bi)) { bv = ov; bi = oj; }
            }
#pragma unroll
            for (int r = 0; r < 5; r++)
                if (i2[r] == bi) v2[r] = FINF;
            if (lane == 0) s_fi[it] = bi;
        }
    }
    __syncthreads();

    if (mode == 0) {
        for (int i = w; i < KNN; i += 8) {
            int rowi = s_fi[i];
            float px = 0.f;
#pragma unroll
            for (int q = 0; q < 4; q++) {
                float4 t = ((const float4*)(T + (size_t)rowi * D))[lane + 32 * q];
                float4 x = ((const float4*)X)[lane + 32 * q];
                ((float4*)g_nb)[i * (D / 4) + lane + 32 * q] = t;
                unsigned blo, bhi;
                CVTB(blo, t.x, t.y);
                CVTB(bhi, t.z, t.w);
                uint2 u; u.x = blo; u.y = bhi;
                *(uint2*)&g_nbh[i * (D / 2) + q * 64 + 2 * lane] = u;
                float a = t.x - x.x, b = t.y - x.y, cc = t.z - x.z, d = t.w - x.w;
                px += a * a + b * b + cc * cc + d * d;
            }
#pragma unroll
            for (int o = 16; o; o >>= 1) px += __shfl_xor_sync(0xffffffffu, px, o);
            if (lane == 0) g_pxk[i] = px;
        }
        for (int i = KNN + w; i < 32; i += 8)
            for (int q = lane; q < D / 2; q += 32) g_nbh[i * (D / 2) + q] = 0u;
    } else {
        for (int j = w; j < KNN; j += 8) {
            int rowj = s_fi[j];
            float s = 0.f;
#pragma unroll
            for (int q = 0; q < 4; q++) {
                float4 t  = ((const float4*)(T + (size_t)rowj * D))[lane + 32 * q];
                float4 nb = ((const float4*)g_nb)[row * (D / 4) + lane + 32 * q];
                float a = t.x - nb.x, b = t.y - nb.y, cc = t.z - nb.z, d = t.w - nb.w;
                s += a * a + b * b + cc * cc + d * d;
            }
#pragma unroll
            for (int o = 16; o; o >>= 1) s += __shfl_xor_sync(0xffffffffu, s, o);
            if (lane == 0) g_sqnn[row * KNN + j] = s;
        }
        __threadfence();
        __syncthreads();
        if (tid == 0) s_last = (atomicAdd(&g_done, 1u) == KNN - 1) ? 1 : 0;
        __syncthreads();
        if (s_last) {
            __threadfence();
            if (tid == 0) g_done = 0;
            if (tid < 32) {
                float norm = 0.f, px = 0.f;
                if (tid < KNN) {
                    float s = 0.f;
#pragma unroll
                    for (int j = 0; j < KNN; j++) s += g_sqnn[tid * KNN + j];
                    norm = sqrtf(s / (float)KNN);
                    px = g_pxk[tid];
                }
#pragma unroll
                for (int o = 16; o; o >>= 1) {
                    norm += __shfl_xor_sync(0xffffffffu, norm, o);
                    px   += __shfl_xor_sync(0xffffffffu, px, o);
                }
                if (tid == 0) {
                    float pdx = sqrtf(px / (float)KNN);
                    float lof = pdx / norm * (float)KNN - 1.f;
                    float r = erff(lof * 0.7071067811865476f);
                    out[0] = fmaxf(r, 0.f);
                }
            }
        }
    }
}

// ---------------- pass 2: R12-proven smem + ldmatrix HMMA GEMM (32-col B) ----------------
#define SA_BYTES 16384
#define SB_OFF   32768
#define SMEM_P2  65536

static __device__ __forceinline__ void mma16816(float* c, const unsigned* a, const unsigned* b) {
    asm volatile(
        "mma.sync.aligned.m16n8k16.row.col.f32.bf16.bf16.f32 "
        "{%0,%1,%2,%3}, {%4,%5,%6,%7}, {%8,%9}, {%0,%1,%2,%3};"
        : "+f"(c[0]), "+f"(c[1]), "+f"(c[2]), "+f"(c[3])
        : "r"(a[0]), "r"(a[1]), "r"(a[2]), "r"(a[3]), "r"(b[0]), "r"(b[1]));
}
static __device__ __forceinline__ void ldsm4(unsigned* r, unsigned addr) {
    asm volatile("ldmatrix.sync.aligned.m8n8.x4.shared.b16 {%0,%1,%2,%3}, [%4];"
                 : "=r"(r[0]), "=r"(r[1]), "=r"(r[2]), "=r"(r[3]) : "r"(addr));
}

__global__ __launch_bounds__(128) void k_pass2(const float* __restrict__ T, int n) {
    extern __shared__ char sh[];
    unsigned sb = (unsigned)__cvta_generic_to_shared(sh);
    int tid = threadIdx.x, lane = tid & 31, w = tid >> 5;
    int qr = lane >> 2, qc = lane & 3;
    int pbase = blockIdx.x * 128;
    int j8 = lane >> 3, r8 = lane & 7;

#pragma unroll
    for (int i = 0; i < 16; i++) {
        int lin = tid + i * 128;
        int nr = lin >> 6, q = lin & 63;
        uint4 v = *(const uint4*)&g_nbh[nr * 256 + q * 4];
        *(uint4*)(sh + SB_OFF + nr * 1024 + ((q ^ (nr & 7)) << 4)) = v;
    }

    float4 r[16];
#define LDG_A(c)                                                                   \
    {                                                                              \
        _Pragma("unroll")                                                          \
        for (int i = 0; i < 8; i++) {                                              \
            int lc = tid + i * 128;                                                \
            int m = lc >> 3, q = lc & 7;                                           \
            int gp = pbase + m; if (gp >= n) gp = n - 1;                           \
            const float4* s4 = (const float4*)(T + (size_t)gp * D + (c) * 64 + q * 8); \
            r[2 * i]     = __ldg(s4);                                              \
            r[2 * i + 1] = __ldg(s4 + 1);                                          \
        }                                                                          \
    }
#define STS_A(bufp)                                                                \
    {                                                                              \
        _Pragma("unroll")                                                          \
        for (int i = 0; i < 8; i++) {                                              \
            int lc = tid + i * 128;                                                \
            int m = lc >> 3, q = lc & 7;                                           \
            uint4 u;                                                               \
            CVTB(u.x, r[2 * i].x,     r[2 * i].y);                                 \
            CVTB(u.y, r[2 * i].z,     r[2 * i].w);                                 \
            CVTB(u.z, r[2 * i + 1].x, r[2 * i + 1].y);                             \
            CVTB(u.w, r[2 * i + 1].z, r[2 * i + 1].w);                             \
            *(uint4*)((bufp) + m * 128 + ((q ^ (m & 7)) << 4)) = u;                \
        }                                                                          \
    }

    LDG_A(0);
    STS_A(sh);
    LDG_A(1);
    __syncthreads();

    float acc[2][4][4];
#pragma unroll
    for (int mt = 0; mt < 2; mt++)
#pragma unroll
        for (int nt = 0; nt < 4; nt++)
#pragma unroll
            for (int q = 0; q < 4; q++) acc[mt][nt][q] = 0.f;

#pragma unroll 1
    for (int c = 0; c < 8; c++) {
        unsigned bufA = sb + (c & 1) * SA_BYTES;
#pragma unroll
        for (int s = 0; s < 4; s++) {
            unsigned af[2][4], bf[2][4];
#pragma unroll
            for (int mt = 0; mt < 2; mt++) {
                int m = w * 32 + mt * 16 + ((j8 & 1) << 3) + r8;
                int q = s * 2 + (j8 >> 1);
                ldsm4(af[mt], bufA + m * 128 + ((q ^ (m & 7)) << 4));
            }
#pragma unroll
            for (int np = 0; np < 2; np++) {
                int nr = np * 16 + ((j8 >> 1) << 3) + r8;
                int q = (c * 4 + s) * 2 + (j8 & 1);
                ldsm4(bf[np], sb + SB_OFF + nr * 1024 + ((q ^ (nr & 7)) << 4));
            }
#pragma unroll
            for (int mt = 0; mt < 2; mt++)
#pragma unroll
                for (int np = 0; np < 2; np++) {
                    mma16816(acc[mt][2 * np],     af[mt], &bf[np][0]);
                    mma16816(acc[mt][2 * np + 1], af[mt], &bf[np][2]);
                }
        }
        if (c + 1 < 8) STS_A(sh + ((c + 1) & 1) * SA_BYTES);
        if (c + 2 < 8) LDG_A(c + 2);
        __syncthreads();
    }

#pragma unroll
    for (int mt = 0; mt < 2; mt++) {
        int p0 = pbase + w * 32 + mt * 16 + qr;
        int p1 = p0 + 8;
        float tn0 = (p0 < n) ? g_tn2[p0] : 0.f;
        float tn1 = (p1 < n) ? g_tn2[p1] : 0.f;
#pragma unroll
        for (int nt = 0; nt < 4; nt++) {
            int k0 = nt * 8 + qc * 2;
            if (k0 < KNN) {
                if (p0 < n) g_sq[(size_t)k0 * n + p0] = tn0 - 2.f * acc[mt][nt][0];
                if (p1 < n) g_sq[(size_t)k0 * n + p1] = tn1 - 2.f * acc[mt][nt][2];
            }
            if (k0 + 1 < KNN) {
                if (p0 < n) g_sq[(size_t)(k0 + 1) * n + p0] = tn0 - 2.f * acc[mt][nt][1];
                if (p1 < n) g_sq[(size_t)(k0 + 1) * n + p1] = tn1 - 2.f * acc[mt][nt][3];
            }
        }
    }
}

// ---------------- launch: 4 nodes ----------------
extern "C" void kernel_launch(void* const* d_in, const int* in_sizes, int n_in,
                              void* d_out, int out_size) {
    const float* A = (const float*)d_in[0];
    const float* B = (const float*)d_in[1];
    const float *X, *T;
    int n;
    if (in_sizes[0] == D) { X = A; T = B; n = in_sizes[1] / D; }
    else                  { X = B; T = A; n = in_sizes[0] / D; }
    if (n > MAXN) n = MAXN;

    int nch = (n + CHUNK - 1) / CHUNK;
    int nbx = (nch + 7) / 8;

    cudaFuncSetAttribute(k_pass2, cudaFuncAttributeMaxDynamicSharedMemorySize, SMEM_P2);

    k_pass1<<<(n + 7) / 8, 256>>>(X, T, n);
    k_topk<<<dim3(nbx, 1), 256>>>(0, n, nch, X, T, (float*)d_out);
    k_pass2<<<(n + 127) / 128, 128, SMEM_P2>>>(T, n);
    k_topk<<<dim3(nbx, KNN), 256>>>(1, n, nch, X, T, (float*)d_out);
}

// round 16
// speedup vs baseline: 1.0373x; 1.0373x over previous
#include <cuda_runtime.h>
#include <cuda_bf16.h>
#include <math.h>

#define D      512
#define KNN    20
#define MAXN   100000
#define MAXCH  256
#define CHUNK  512
#define RPL    16
#define FINF   3.0e38f
#define CAP    8192
#define HGX    14          // blocks per row for H1/H2/H3

// ---------------- persistent scratch ----------------
__device__ float g_tn2[MAXN];
__device__ float g_score[MAXN];
__device__ float g_sq[KNN * MAXN];
__device__ float g_cand_d[MAXCH * KNN];     // X-row stage-A candidates
__device__ int   g_cand_i[MAXCH * KNN];
__device__ float g_nb[KNN * D];
__device__ float g_pxk[KNN];
__device__ float g_sqnn[KNN * KNN];
__device__ unsigned g_nbh[32 * (D / 2)];
__device__ unsigned g_rowdone0;             // topk0 last-block counter
__device__ unsigned g_done;                 // final counter
__device__ unsigned g_hist1[KNN * 256];
__device__ unsigned g_hist2[KNN * 256];
__device__ unsigned g_b1[KNN], g_cb1[KNN], g_thr[KNN];
__device__ unsigned g_ccnt[KNN];
__device__ float g_cv2[KNN * CAP];
__device__ int   g_ci2[KNN * CAP];
__device__ unsigned g_d1[KNN], g_d2[KNN], g_d3[KNN];

#define CVTB(res, lo, hi) \
    asm("cvt.rn.bf16x2.f32 %0, %1, %2;" : "=r"(res) : "f"(hi), "f"(lo))

static __device__ __forceinline__ unsigned fmono(float f) {
    unsigned u = __float_as_uint(f);
    return (u & 0x80000000u) ? ~u : (u | 0x80000000u);
}

// ---------------- pass 1 ----------------
__global__ void k_pass1(const float* __restrict__ X, const float* __restrict__ T, int n) {
    int w    = blockIdx.x * (blockDim.x >> 5) + (threadIdx.x >> 5);
    int lane = threadIdx.x & 31;
    if (w >= n) return;
    const float4* row = (const float4*)(T + (size_t)w * D);
    const float4* xv  = (const float4*)X;
    float tn2 = 0.f, dx = 0.f;
#pragma unroll
    for (int i = 0; i < 4; i++) {
        float4 t = row[lane + 32 * i];
        float4 x = __ldg(&xv[lane + 32 * i]);
        tn2 += t.x * t.x + t.y * t.y + t.z * t.z + t.w * t.w;
        dx  += t.x * x.x + t.y * x.y + t.z * x.z + t.w * x.w;
    }
#pragma unroll
    for (int o = 16; o; o >>= 1) {
        tn2 += __shfl_xor_sync(0xffffffffu, tn2, o);
        dx  += __shfl_xor_sync(0xffffffffu, dx, o);
    }
    if (lane == 0) { g_tn2[w] = tn2; g_score[w] = tn2 - 2.f * dx; }
}

// ---------------- topk0: X-row knn + gather (fused, last-block) ----------------
__global__ void k_topk0(int n, int nch, const float* __restrict__ X,
                        const float* __restrict__ T) {
    int tid = threadIdx.x, lane = tid & 31, w = tid >> 5;
    int c = blockIdx.x * 8 + w;
    int nbx = gridDim.x;
    __shared__ float s_cv[8 * KNN];
    __shared__ int   s_ci[8 * KNN];
    __shared__ int   s_fi[KNN];
    __shared__ int   s_last;

    if (c < nch) {
        const float* v = g_score;
        int base = c * CHUNK;
        float val[RPL];
#pragma unroll
        for (int r = 0; r < RPL; r++) {
            int g = base + lane + 32 * r;
            val[r] = (g < n) ? v[g] : FINF;
        }
        float* od = g_cand_d + (size_t)c * KNN;
        int*   oi = g_cand_i + (size_t)c * KNN;
        int ibase = base + lane;
        for (int it = 0; it < KNN; it++) {
            float bv = val[0]; int br = 0;
#pragma unroll
            for (int r = 1; r < RPL; r++)
                if (val[r] < bv) { bv = val[r]; br = r; }
            int bi = (bv >= FINF) ? 0x7fffffff : (ibase + (br << 5));
#pragma unroll
            for (int o = 16; o; o >>= 1) {
                float ov = __shfl_xor_sync(0xffffffffu, bv, o);
                int   oj = __shfl_xor_sync(0xffffffffu, bi, o);
                if (ov < bv || (ov == bv && oj < bi)) { bv = ov; bi = oj; }
            }
            int rel = bi - ibase;
#pragma unroll
            for (int r = 0; r < RPL; r++)
                if (rel == (r << 5)) val[r] = FINF;
            if (lane == 0) { od[it] = bv; oi[it] = bi; }
        }
    }
    __threadfence();
    __syncthreads();
    if (tid == 0) s_last = (atomicAdd(&g_rowdone0, 1u) == (unsigned)(nbx - 1)) ? 1 : 0;
    __syncthreads();
    if (!s_last) return;
    if (tid == 0) g_rowdone0 = 0;

    int m = nch * KNN;
    float val[RPL]; int idx[RPL];
#pragma unroll
    for (int r = 0; r < RPL; r++) {
        int j = w * 512 + lane + 32 * r;
        bool ok = j < m;
        val[r] = ok ? g_cand_d[j] : FINF;
        idx[r] = ok ? g_cand_i[j] : 0x7fffffff;
    }
    for (int it = 0; it < KNN; it++) {
        float bv = val[0]; int bi = idx[0];
#pragma unroll
        for (int r = 1; r < RPL; r++)
            if (val[r] < bv || (val[r] == bv && idx[r] < bi)) { bv = val[r]; bi = idx[r]; }
#pragma unroll
        for (int o = 16; o; o >>= 1) {
            float ov = __shfl_xor_sync(0xffffffffu, bv, o);
            int   oj = __shfl_xor_sync(0xffffffffu, bi, o);
            if (ov < bv || (ov == bv && oj < bi)) { bv = ov; bi = oj; }
        }
#pragma unroll
        for (int r = 0; r < RPL; r++)
            if (idx[r] == bi) val[r] = FINF;
        if (lane == 0) { s_cv[w * KNN + it] = bv; s_ci[w * KNN + it] = bi; }
    }
    __syncthreads();
    if (w == 0) {
        float v2[5]; int i2[5];
#pragma unroll
        for (int r = 0; r < 5; r++) { int j = lane + 32 * r; v2[r] = s_cv[j]; i2[r] = s_ci[j]; }
        for (int it = 0; it < KNN; it++) {
            float bv = v2[0]; int bi = i2[0];
#pragma unroll
            for (int r = 1; r < 5; r++)
                if (v2[r] < bv || (v2[r] == bv && i2[r] < bi)) { bv = v2[r]; bi = i2[r]; }
#pragma unroll
            for (int o = 16; o; o >>= 1) {
                float ov = __shfl_xor_sync(0xffffffffu, bv, o);
                int   oj = __shfl_xor_sync(0xffffffffu, bi, o);
                if (ov < bv || (ov == bv && oj < bi)) { bv = ov; bi = oj; }
            }
#pragma unroll
            for (int r = 0; r < 5; r++)
                if (i2[r] == bi) v2[r] = FINF;
            if (lane == 0) s_fi[it] = bi;
        }
    }
    __syncthreads();

    for (int i = w; i < KNN; i += 8) {
        int rowi = s_fi[i];
        float px = 0.f;
#pragma unroll
        for (int q = 0; q < 4; q++) {
            float4 t = ((const float4*)(T + (size_t)rowi * D))[lane + 32 * q];
            float4 x = ((const float4*)X)[lane + 32 * q];
            ((float4*)g_nb)[i * (D / 4) + lane + 32 * q] = t;
            unsigned blo, bhi;
            CVTB(blo, t.x, t.y);
            CVTB(bhi, t.z, t.w);
            uint2 u; u.x = blo; u.y = bhi;
            *(uint2*)&g_nbh[i * (D / 2) + q * 64 + 2 * lane] = u;
            float a = t.x - x.x, b = t.y - x.y, cc = t.z - x.z, d = t.w - x.w;
            px += a * a + b * b + cc * cc + d * d;
        }
#pragma unroll
        for (int o = 16; o; o >>= 1) px += __shfl_xor_sync(0xffffffffu, px, o);
        if (lane == 0) g_pxk[i] = px;
    }
    for (int i = KNN + w; i < 32; i += 8)
        for (int q = lane; q < D / 2; q += 32) g_nbh[i * (D / 2) + q] = 0u;
}

// ---------------- H1: 256-bin histogram of top-8 bits ----------------
__global__ void k_h1(int n) {
    int row = blockIdx.y, tid = threadIdx.x, lane = tid & 31;
    __shared__ unsigned hb[256];
    __shared__ int s_last;
    if (tid < 256) hb[tid] = 0;
    __syncthreads();
    const float* v = g_sq + (size_t)row * n;
    for (int i = blockIdx.x * 256 + tid; i < n; i += HGX * 256) {
        unsigned b = fmono(v[i]) >> 24;
        unsigned am = __activemask();
        unsigned mk = __match_any_sync(am, b);
        if (lane == __ffs(mk) - 1) atomicAdd(&hb[b], __popc(mk));
    }
    __syncthreads();
    if (tid < 256 && hb[tid]) atomicAdd(&g_hist1[row * 256 + tid], hb[tid]);
    __threadfence();
    __syncthreads();
    if (tid == 0) s_last = (atomicAdd(&g_d1[row], 1u) == HGX - 1) ? 1 : 0;
    __syncthreads();
    if (!s_last) return;
    if (tid == 0) g_d1[row] = 0;
    if (tid < 256) hb[tid] = g_hist1[row * 256 + tid];
    __syncthreads();
    if (tid < 32) {
        unsigned loc[8], L = 0;
#pragma unroll
        for (int i = 0; i < 8; i++) { loc[i] = hb[tid * 8 + i]; L += loc[i]; }
        unsigned inc = L;
#pragma unroll
        for (int o = 1; o < 32; o <<= 1) {
            unsigned t = __shfl_up_sync(0xffffffffu, inc, o);
            if (tid >= o) inc += t;
        }
        unsigned pre = inc - L;
        if (pre < KNN && pre + L >= KNN) {
            unsigned cc = pre;
#pragma unroll
            for (int i = 0; i < 8; i++) {
                if (cc < KNN && cc + loc[i] >= KNN) { g_b1[row] = tid * 8 + i; g_cb1[row] = cc; }
                cc += loc[i];
            }
        }
    }
}

// ---------------- H2: refine with next 8 bits ----------------
__global__ void k_h2(int n) {
    int row = blockIdx.y, tid = threadIdx.x, lane = tid & 31;
    __shared__ unsigned hb[256];
    __shared__ int s_last;
    if (tid < 256) hb[tid] = 0;
    __syncthreads();
    unsigned b1 = g_b1[row];
    const float* v = g_sq + (size_t)row * n;
    for (int i = blockIdx.x * 256 + tid; i < n; i += HGX * 256) {
        unsigned u = fmono(v[i]);
        if ((u >> 24) == b1) {
            unsigned b = (u >> 16) & 255u;
            unsigned am = __activemask();
            unsigned mk = __match_any_sync(am, b);
            if (lane == __ffs(mk) - 1) atomicAdd(&hb[b], __popc(mk));
        }
    }
    __syncthreads();
    if (tid < 256 && hb[tid]) atomicAdd(&g_hist2[row * 256 + tid], hb[tid]);
    __threadfence();
    __syncthreads();
    if (tid == 0) s_last = (atomicAdd(&g_d2[row], 1u) == HGX - 1) ? 1 : 0;
    __syncthreads();
    if (!s_last) return;
    if (tid == 0) g_d2[row] = 0;
    if (tid < 256) hb[tid] = g_hist2[row * 256 + tid];
    __syncthreads();
    if (tid < 32) {
        unsigned base = g_cb1[row];
        unsigned loc[8], L = 0;
#pragma unroll
        for (int i = 0; i < 8; i++) { loc[i] = hb[tid * 8 + i]; L += loc[i]; }
        unsigned inc = L;
#pragma unroll
        for (int o = 1; o < 32; o <<= 1) {
            unsigned t = __shfl_up_sync(0xffffffffu, inc, o);
            if (tid >= o) inc += t;
        }
        unsigned pre = base + inc - L;
        if (pre < KNN && pre + L >= KNN) {
            unsigned cc = pre;
#pragma unroll
            for (int i = 0; i < 8; i++) {
                if (cc < KNN && cc + loc[i] >= KNN)
                    g_thr[row] = (g_b1[row] << 8) | (tid * 8 + i);
                cc += loc[i];
            }
        }
    }
}

// ---------------- H3: gather candidates, exact top-20, sqnn, final ----------------
__global__ void k_h3(int n, const float* __restrict__ T, float* out) {
    extern __shared__ char dsm[];
    float* sv = (float*)dsm;            // [CAP]
    int*   si = (int*)(dsm + 4 * CAP);  // [CAP]
    int row = blockIdx.y, tid = threadIdx.x, lane = tid & 31, w = tid >> 5;
    __shared__ int   s_fi[KNN];
    __shared__ float wv[8]; __shared__ int wi[8], wp[8];
    __shared__ int s_last;

    unsigned thr = g_thr[row];
    const float* v = g_sq + (size_t)row * n;
    for (int i = blockIdx.x * 256 + tid; i < n; i += HGX * 256) {
        float f = v[i];
        if ((fmono(f) >> 16) <= thr) {
            unsigned p = atomicAdd(&g_ccnt[row], 1u);
            if (p < CAP) { g_cv2[row * CAP + p] = f; g_ci2[row * CAP + p] = i; }
        }
    }
    __threadfence();
    __syncthreads();
    if (tid == 0) s_last = (atomicAdd(&g_d3[row], 1u) == HGX - 1) ? 1 : 0;
    __syncthreads();
    if (!s_last) return;
    if (tid == 0) g_d3[row] = 0;

    int cnt = (int)g_ccnt[row];
    if (cnt > CAP) cnt = CAP;
    for (int j = tid; j < cnt; j += 256) {
        sv[j] = g_cv2[row * CAP + j];
        si[j] = g_ci2[row * CAP + j];
    }
    // resets for next replay
    if (tid == 0) g_ccnt[row] = 0;
    if (tid < 256) { g_hist1[row * 256 + tid] = 0; g_hist2[row * 256 + tid] = 0; }
    __syncthreads();

    for (int it = 0; it < KNN; it++) {
        float bv = FINF; int bi = 0x7fffffff; int bp = -1;
        for (int j = tid; j < cnt; j += 256) {
            float x = sv[j]; int xi = si[j];
            if (x < bv || (x == bv && xi < bi)) { bv = x; bi = xi; bp = j; }
        }
#pragma unroll
        for (int o = 16; o; o >>= 1) {
            float ov = __shfl_xor_sync(0xffffffffu, bv, o);
            int   oi = __shfl_xor_sync(0xffffffffu, bi, o);
            int   op = __shfl_xor_sync(0xffffffffu, bp, o);
            if (ov < bv || (ov == bv && oi < bi)) { bv = ov; bi = oi; bp = op; }
        }
        if (lane == 0) { wv[w] = bv; wi[w] = bi; wp[w] = bp; }
        __syncthreads();
        if (tid == 0) {
            float fv = wv[0]; int fi = wi[0]; int fp = wp[0];
#pragma unroll
            for (int q = 1; q < 8; q++)
                if (wv[q] < fv || (wv[q] == fv && wi[q] < fi)) { fv = wv[q]; fi = wi[q]; fp = wp[q]; }
            s_fi[it] = fi;
            if (fp >= 0) sv[fp] = FINF;
        }
        __syncthreads();
    }

    // sqnn epilogue
    for (int j = w; j < KNN; j += 8) {
        int rowj = s_fi[j];
        float s = 0.f;
#pragma unroll
        for (int q = 0; q < 4; q++) {
            float4 t  = ((const float4*)(T + (size_t)rowj * D))[lane + 32 * q];
            float4 nb = ((const float4*)g_nb)[row * (D / 4) + lane + 32 * q];
            float a = t.x - nb.x, b = t.y - nb.y, cc = t.z - nb.z, d = t.w - nb.w;
            s += a * a + b * b + cc * cc + d * d;
        }
#pragma unroll
        for (int o = 16; o; o >>= 1) s += __shfl_xor_sync(0xffffffffu, s, o);
        if (lane == 0) g_sqnn[row * KNN + j] = s;
    }
    __threadfence();
    __syncthreads();
    if (tid == 0) s_last = (atomicAdd(&g_done, 1u) == KNN - 1) ? 1 : 0;
    __syncthreads();
    if (s_last) {
        __threadfence();
        if (tid == 0) g_done = 0;
        if (tid < 32) {
            float norm = 0.f, px = 0.f;
            if (tid < KNN) {
                float s = 0.f;
#pragma unroll
                for (int j = 0; j < KNN; j++) s += g_sqnn[tid * KNN + j];
                norm = sqrtf(s / (float)KNN);
                px = g_pxk[tid];
            }
#pragma unroll
            for (int o = 16; o; o >>= 1) {
                norm += __shfl_xor_sync(0xffffffffu, norm, o);
                px   += __shfl_xor_sync(0xffffffffu, px, o);
            }
            if (tid == 0) {
                float pdx = sqrtf(px / (float)KNN);
                float lof = pdx / norm * (float)KNN - 1.f;
                float r = erff(lof * 0.7071067811865476f);
                out[0] = fmaxf(r, 0.f);
            }
        }
    }
}

// ---------------- pass 2: R12-proven smem + ldmatrix HMMA GEMM ----------------
#define SA_BYTES 16384
#define SB_OFF   32768
#define SMEM_P2  65536

static __device__ __forceinline__ void mma16816(float* c, const unsigned* a, const unsigned* b) {
    asm volatile(
        "mma.sync.aligned.m16n8k16.row.col.f32.bf16.bf16.f32 "
        "{%0,%1,%2,%3}, {%4,%5,%6,%7}, {%8,%9}, {%0,%1,%2,%3};"
        : "+f"(c[0]), "+f"(c[1]), "+f"(c[2]), "+f"(c[3])
        : "r"(a[0]), "r"(a[1]), "r"(a[2]), "r"(a[3]), "r"(b[0]), "r"(b[1]));
}
static __device__ __forceinline__ void ldsm4(unsigned* r, unsigned addr) {
    asm volatile("ldmatrix.sync.aligned.m8n8.x4.shared.b16 {%0,%1,%2,%3}, [%4];"
                 : "=r"(r[0]), "=r"(r[1]), "=r"(r[2]), "=r"(r[3]) : "r"(addr));
}

__global__ __launch_bounds__(128) void k_pass2(const float* __restrict__ T, int n) {
    extern __shared__ char sh[];
    unsigned sb = (unsigned)__cvta_generic_to_shared(sh);
    int tid = threadIdx.x, lane = tid & 31, w = tid >> 5;
    int qr = lane >> 2, qc = lane & 3;
    int pbase = blockIdx.x * 128;
    int j8 = lane >> 3, r8 = lane & 7;

#pragma unroll
    for (int i = 0; i < 16; i++) {
        int lin = tid + i * 128;
        int nr = lin >> 6, q = lin & 63;
        uint4 v = *(const uint4*)&g_nbh[nr * 256 + q * 4];
        *(uint4*)(sh + SB_OFF + nr * 1024 + ((q ^ (nr & 7)) << 4)) = v;
    }

    float4 r[16];
#define LDG_A(c)                                                                   \
    {                                                                              \
        _Pragma("unroll")                                                          \
        for (int i = 0; i < 8; i++) {                                              \
            int lc = tid + i * 128;                                                \
            int m = lc >> 3, q = lc & 7;                                           \
            int gp = pbase + m; if (gp >= n) gp = n - 1;                           \
            const float4* s4 = (const float4*)(T + (size_t)gp * D + (c) * 64 + q * 8); \
            r[2 * i]     = __ldg(s4);                                              \
            r[2 * i + 1] = __ldg(s4 + 1);                                          \
        }                                                                          \
    }
#define STS_A(bufp)                                                                \
    {                                                                              \
        _Pragma("unroll")                                                          \
        for (int i = 0; i < 8; i++) {                                              \
            int lc = tid + i * 128;                                                \
            int m = lc >> 3, q = lc & 7;                                           \
            uint4 u;                                                               \
            CVTB(u.x, r[2 * i].x,     r[2 * i].y);                                 \
            CVTB(u.y, r[2 * i].z,     r[2 * i].w);                                 \
            CVTB(u.z, r[2 * i + 1].x, r[2 * i + 1].y);                             \
            CVTB(u.w, r[2 * i + 1].z, r[2 * i + 1].w);                             \
            *(uint4*)((bufp) + m * 128 + ((q ^ (m & 7)) << 4)) = u;                \
        }                                                                          \
    }

    LDG_A(0);
    STS_A(sh);
    LDG_A(1);
    __syncthreads();

    float acc[2][4][4];
#pragma unroll
    for (int mt = 0; mt < 2; mt++)
#pragma unroll
        for (int nt = 0; nt < 4; nt++)
#pragma unroll
            for (int q = 0; q < 4; q++) acc[mt][nt][q] = 0.f;

#pragma unroll 1
    for (int c = 0; c < 8; c++) {
        unsigned bufA = sb + (c & 1) * SA_BYTES;
#pragma unroll
        for (int s = 0; s < 4; s++) {
            unsigned af[2][4], bf[2][4];
#pragma unroll
            for (int mt = 0; mt < 2; mt++) {
                int m = w * 32 + mt * 16 + ((j8 & 1) << 3) + r8;
                int q = s * 2 + (j8 >> 1);
                ldsm4(af[mt], bufA + m * 128 + ((q ^ (m & 7)) << 4));
            }
#pragma unroll
            for (int np = 0; np < 2; np++) {
                int nr = np * 16 + ((j8 >> 1) << 3) + r8;
                int q = (c * 4 + s) * 2 + (j8 & 1);
                ldsm4(bf[np], sb + SB_OFF + nr * 1024 + ((q ^ (nr & 7)) << 4));
            }
#pragma unroll
            for (int mt = 0; mt < 2; mt++)
#pragma unroll
                for (int np = 0; np < 2; np++) {
                    mma16816(acc[mt][2 * np],     af[mt], &bf[np][0]);
                    mma16816(acc[mt][2 * np + 1], af[mt], &bf[np][2]);
                }
        }
        if (c + 1 < 8) STS_A(sh + ((c + 1) & 1) * SA_BYTES);
        if (c + 2 < 8) LDG_A(c + 2);
        __syncthreads();
    }

#pragma unroll
    for (int mt = 0; mt < 2; mt++) {
        int p0 = pbase + w * 32 + mt * 16 + qr;
        int p1 = p0 + 8;
        float tn0 = (p0 < n) ? g_tn2[p0] : 0.f;
        float tn1 = (p1 < n) ? g_tn2[p1] : 0.f;
#pragma unroll
        for (int nt = 0; nt < 4; nt++) {
            int k0 = nt * 8 + qc * 2;
            if (k0 < KNN) {
                if (p0 < n) g_sq[(size_t)k0 * n + p0] = tn0 - 2.f * acc[mt][nt][0];
                if (p1 < n) g_sq[(size_t)k0 * n + p1] = tn1 - 2.f * acc[mt][nt][2];
            }
            if (k0 + 1 < KNN) {
                if (p0 < n) g_sq[(size_t)(k0 + 1) * n + p0] = tn0 - 2.f * acc[mt][nt][1];
                if (p1 < n) g_sq[(size_t)(k0 + 1) * n + p1] = tn1 - 2.f * acc[mt][nt][3];
            }
        }
    }
}

// ---------------- launch: 6 nodes ----------------
extern "C" void kernel_launch(void* const* d_in, const int* in_sizes, int n_in,
                              void* d_out, int out_size) {
    const float* A = (const float*)d_in[0];
    const float* B = (const float*)d_in[1];
    const float *X, *T;
    int n;
    if (in_sizes[0] == D) { X = A; T = B; n = in_sizes[1] / D; }
    else                  { X = B; T = A; n = in_sizes[0] / D; }
    if (n > MAXN) n = MAXN;

    int nch = (n + CHUNK - 1) / CHUNK;
    int nbx = (nch + 7) / 8;

    cudaFuncSetAttribute(k_pass2, cudaFuncAttributeMaxDynamicSharedMemorySize, SMEM_P2);
    cudaFuncSetAttribute(k_h3, cudaFuncAttributeMaxDynamicSharedMemorySize, CAP * 8);

    k_pass1<<<(n + 7) / 8, 256>>>(X, T, n);
    k_topk0<<<nbx, 256>>>(n, nch, X, T);
    k_pass2<<<(n + 127) / 128, 128, SMEM_P2>>>(T, n);
    k_h1<<<dim3(HGX, KNN), 256>>>(n);
    k_h2<<<dim3(HGX, KNN), 256>>>(n);
    k_h3<<<dim3(HGX, KNN), 256, CAP * 8>>>(n, T, (float*)d_out);
}

// round 17
// speedup vs baseline: 1.1368x; 1.0959x over previous
#include <cuda_runtime.h>
#include <cuda_bf16.h>
#include <math.h>

#define D      512
#define KNN    20
#define MAXN   100000
#define MAXCH  256
#define CHUNK  512
#define RPL    16
#define FINF   3.0e38f
#define CAP    8192
#define HGX    25          // blocks per row for H1/H2/H3

// ---------------- persistent scratch ----------------
__device__ float g_tn2[MAXN];
__device__ float g_score[MAXN];
__device__ float g_sq[KNN * MAXN];
__device__ float g_cand_d[MAXCH * KNN];     // X-row stage-A candidates
__device__ int   g_cand_i[MAXCH * KNN];
__device__ float g_nb[KNN * D];
__device__ float g_pxk[KNN];
__device__ float g_sqnn[KNN * KNN];
__device__ unsigned g_nbh[32 * (D / 2)];
__device__ unsigned g_rowdone0;             // topk0 last-block counter
__device__ unsigned g_done;                 // final counter
__device__ unsigned g_hist1[KNN * 256];
__device__ unsigned g_hist2[KNN * 256];
__device__ unsigned g_b1[KNN], g_cb1[KNN], g_thr[KNN];
__device__ unsigned g_ccnt[KNN];
__device__ float g_cv2[KNN * CAP];
__device__ int   g_ci2[KNN * CAP];
__device__ unsigned g_d1[KNN], g_d2[KNN], g_d3[KNN];

#define CVTB(res, lo, hi) \
    asm("cvt.rn.bf16x2.f32 %0, %1, %2;" : "=r"(res) : "f"(hi), "f"(lo))

static __device__ __forceinline__ unsigned fmono(float f) {
    unsigned u = __float_as_uint(f);
    return (u & 0x80000000u) ? ~u : (u | 0x80000000u);
}

// MLP-8 vectorized slab load: 8 contiguous floats per thread (2x LDG.128)
static __device__ __forceinline__ void load8(const float* __restrict__ v, int i0, int n,
                                             float* x) {
    if (i0 + 8 <= n) {
        float4 a = *(const float4*)(v + i0);
        float4 b = *(const float4*)(v + i0 + 4);
        x[0] = a.x; x[1] = a.y; x[2] = a.z; x[3] = a.w;
        x[4] = b.x; x[5] = b.y; x[6] = b.z; x[7] = b.w;
    } else {
#pragma unroll
        for (int j = 0; j < 8; j++) x[j] = (i0 + j < n) ? v[i0 + j] : FINF;
    }
}

// ---------------- pass 1 ----------------
__global__ void k_pass1(const float* __restrict__ X, const float* __restrict__ T, int n) {
    int w    = blockIdx.x * (blockDim.x >> 5) + (threadIdx.x >> 5);
    int lane = threadIdx.x & 31;
    if (w >= n) return;
    const float4* row = (const float4*)(T + (size_t)w * D);
    const float4* xv  = (const float4*)X;
    float tn2 = 0.f, dx = 0.f;
#pragma unroll
    for (int i = 0; i < 4; i++) {
        float4 t = row[lane + 32 * i];
        float4 x = __ldg(&xv[lane + 32 * i]);
        tn2 += t.x * t.x + t.y * t.y + t.z * t.z + t.w * t.w;
        dx  += t.x * x.x + t.y * x.y + t.z * x.z + t.w * x.w;
    }
#pragma unroll
    for (int o = 16; o; o >>= 1) {
        tn2 += __shfl_xor_sync(0xffffffffu, tn2, o);
        dx  += __shfl_xor_sync(0xffffffffu, dx, o);
    }
    if (lane == 0) { g_tn2[w] = tn2; g_score[w] = tn2 - 2.f * dx; }
}

// ---------------- topk0: X-row knn + gather (fused, last-block) ----------------
__global__ void k_topk0(int n, int nch, const float* __restrict__ X,
                        const float* __restrict__ T) {
    int tid = threadIdx.x, lane = tid & 31, w = tid >> 5;
    int c = blockIdx.x * 8 + w;
    int nbx = gridDim.x;
    __shared__ float s_cv[8 * KNN];
    __shared__ int   s_ci[8 * KNN];
    __shared__ int   s_fi[KNN];
    __shared__ int   s_last;

    if (c < nch) {
        const float* v = g_score;
        int base = c * CHUNK;
        float val[RPL];
#pragma unroll
        for (int r = 0; r < RPL; r++) {
            int g = base + lane + 32 * r;
            val[r] = (g < n) ? v[g] : FINF;
        }
        float* od = g_cand_d + (size_t)c * KNN;
        int*   oi = g_cand_i + (size_t)c * KNN;
        int ibase = base + lane;
        for (int it = 0; it < KNN; it++) {
            float bv = val[0]; int br = 0;
#pragma unroll
            for (int r = 1; r < RPL; r++)
                if (val[r] < bv) { bv = val[r]; br = r; }
            int bi = (bv >= FINF) ? 0x7fffffff : (ibase + (br << 5));
#pragma unroll
            for (int o = 16; o; o >>= 1) {
                float ov = __shfl_xor_sync(0xffffffffu, bv, o);
                int   oj = __shfl_xor_sync(0xffffffffu, bi, o);
                if (ov < bv || (ov == bv && oj < bi)) { bv = ov; bi = oj; }
            }
            int rel = bi - ibase;
#pragma unroll
            for (int r = 0; r < RPL; r++)
                if (rel == (r << 5)) val[r] = FINF;
            if (lane == 0) { od[it] = bv; oi[it] = bi; }
        }
    }
    __threadfence();
    __syncthreads();
    if (tid == 0) s_last = (atomicAdd(&g_rowdone0, 1u) == (unsigned)(nbx - 1)) ? 1 : 0;
    __syncthreads();
    if (!s_last) return;
    if (tid == 0) g_rowdone0 = 0;

    int m = nch * KNN;
    float val[RPL]; int idx[RPL];
#pragma unroll
    for (int r = 0; r < RPL; r++) {
        int j = w * 512 + lane + 32 * r;
        bool ok = j < m;
        val[r] = ok ? g_cand_d[j] : FINF;
        idx[r] = ok ? g_cand_i[j] : 0x7fffffff;
    }
    for (int it = 0; it < KNN; it++) {
        float bv = val[0]; int bi = idx[0];
#pragma unroll
        for (int r = 1; r < RPL; r++)
            if (val[r] < bv || (val[r] == bv && idx[r] < bi)) { bv = val[r]; bi = idx[r]; }
#pragma unroll
        for (int o = 16; o; o >>= 1) {
            float ov = __shfl_xor_sync(0xffffffffu, bv, o);
            int   oj = __shfl_xor_sync(0xffffffffu, bi, o);
            if (ov < bv || (ov == bv && oj < bi)) { bv = ov; bi = oj; }
        }
#pragma unroll
        for (int r = 0; r < RPL; r++)
            if (idx[r] == bi) val[r] = FINF;
        if (lane == 0) { s_cv[w * KNN + it] = bv; s_ci[w * KNN + it] = bi; }
    }
    __syncthreads();
    if (w == 0) {
        float v2[5]; int i2[5];
#pragma unroll
        for (int r = 0; r < 5; r++) { int j = lane + 32 * r; v2[r] = s_cv[j]; i2[r] = s_ci[j]; }
        for (int it = 0; it < KNN; it++) {
            float bv = v2[0]; int bi = i2[0];
#pragma unroll
            for (int r = 1; r < 5; r++)
                if (v2[r] < bv || (v2[r] == bv && i2[r] < bi)) { bv = v2[r]; bi = i2[r]; }
#pragma unroll
            for (int o = 16; o; o >>= 1) {
                float ov = __shfl_xor_sync(0xffffffffu, bv, o);
                int   oj = __shfl_xor_sync(0xffffffffu, bi, o);
                if (ov < bv || (ov == bv && oj < bi)) { bv = ov; bi = oj; }
            }
#pragma unroll
            for (int r = 0; r < 5; r++)
                if (i2[r] == bi) v2[r] = FINF;
            if (lane == 0) s_fi[it] = bi;
        }
    }
    __syncthreads();

    for (int i = w; i < KNN; i += 8) {
        int rowi = s_fi[i];
        float px = 0.f;
#pragma unroll
        for (int q = 0; q < 4; q++) {
            float4 t = ((const float4*)(T + (size_t)rowi * D))[lane + 32 * q];
            float4 x = ((const float4*)X)[lane + 32 * q];
            ((float4*)g_nb)[i * (D / 4) + lane + 32 * q] = t;
            unsigned blo, bhi;
            CVTB(blo, t.x, t.y);
            CVTB(bhi, t.z, t.w);
            uint2 u; u.x = blo; u.y = bhi;
            *(uint2*)&g_nbh[i * (D / 2) + q * 64 + 2 * lane] = u;
            float a = t.x - x.x, b = t.y - x.y, cc = t.z - x.z, d = t.w - x.w;
            px += a * a + b * b + cc * cc + d * d;
        }
#pragma unroll
        for (int o = 16; o; o >>= 1) px += __shfl_xor_sync(0xffffffffu, px, o);
        if (lane == 0) g_pxk[i] = px;
    }
    for (int i = KNN + w; i < 32; i += 8)
        for (int q = lane; q < D / 2; q += 32) g_nbh[i * (D / 2) + q] = 0u;
}

// ---------------- H1: 256-bin histogram of top-8 bits (MLP-8) ----------------
__global__ void k_h1(int n) {
    int row = blockIdx.y, tid = threadIdx.x, lane = tid & 31;
    __shared__ unsigned hb[256];
    __shared__ int s_last;
    if (tid < 256) hb[tid] = 0;
    __syncthreads();
    const float* v = g_sq + (size_t)row * n;
    for (int base = blockIdx.x * 2048; base < n; base += HGX * 2048) {
        int i0 = base + tid * 8;
        float x[8];
        load8(v, i0, n, x);
#pragma unroll
        for (int j = 0; j < 8; j++) {
            unsigned b = fmono(x[j]) >> 24;
            unsigned am = __activemask();
            unsigned mk = __match_any_sync(am, b);
            if (lane == __ffs(mk) - 1) atomicAdd(&hb[b], __popc(mk));
        }
    }
    __syncthreads();
    if (tid < 256 && hb[tid]) atomicAdd(&g_hist1[row * 256 + tid], hb[tid]);
    __threadfence();
    __syncthreads();
    if (tid == 0) s_last = (atomicAdd(&g_d1[row], 1u) == HGX - 1) ? 1 : 0;
    __syncthreads();
    if (!s_last) return;
    if (tid == 0) g_d1[row] = 0;
    if (tid < 256) hb[tid] = g_hist1[row * 256 + tid];
    __syncthreads();
    if (tid < 32) {
        unsigned loc[8], L = 0;
#pragma unroll
        for (int i = 0; i < 8; i++) { loc[i] = hb[tid * 8 + i]; L += loc[i]; }
        unsigned inc = L;
#pragma unroll
        for (int o = 1; o < 32; o <<= 1) {
            unsigned t = __shfl_up_sync(0xffffffffu, inc, o);
            if (tid >= o) inc += t;
        }
        unsigned pre = inc - L;
        if (pre < KNN && pre + L >= KNN) {
            unsigned cc = pre;
#pragma unroll
            for (int i = 0; i < 8; i++) {
                if (cc < KNN && cc + loc[i] >= KNN) { g_b1[row] = tid * 8 + i; g_cb1[row] = cc; }
                cc += loc[i];
            }
        }
    }
}

// ---------------- H2: refine with next 8 bits (MLP-8) ----------------
__global__ void k_h2(int n) {
    int row = blockIdx.y, tid = threadIdx.x, lane = tid & 31;
    __shared__ unsigned hb[256];
    __shared__ int s_last;
    if (tid < 256) hb[tid] = 0;
    __syncthreads();
    unsigned b1 = g_b1[row];
    const float* v = g_sq + (size_t)row * n;
    for (int base = blockIdx.x * 2048; base < n; base += HGX * 2048) {
        int i0 = base + tid * 8;
        float x[8];
        load8(v, i0, n, x);
#pragma unroll
        for (int j = 0; j < 8; j++) {
            unsigned u = fmono(x[j]);
            bool in = (u >> 24) == b1;
            unsigned am = __activemask();
            unsigned inm = __ballot_sync(am, in);
            if (in) {
                unsigned b = (u >> 16) & 255u;
                unsigned mk = __match_any_sync(am & inm, b);
                if (lane == __ffs(mk) - 1) atomicAdd(&hb[b], __popc(mk));
            }
        }
    }
    __syncthreads();
    if (tid < 256 && hb[tid]) atomicAdd(&g_hist2[row * 256 + tid], hb[tid]);
    __threadfence();
    __syncthreads();
    if (tid == 0) s_last = (atomicAdd(&g_d2[row], 1u) == HGX - 1) ? 1 : 0;
    __syncthreads();
    if (!s_last) return;
    if (tid == 0) g_d2[row] = 0;
    if (tid < 256) hb[tid] = g_hist2[row * 256 + tid];
    __syncthreads();
    if (tid < 32) {
        unsigned base = g_cb1[row];
        unsigned loc[8], L = 0;
#pragma unroll
        for (int i = 0; i < 8; i++) { loc[i] = hb[tid * 8 + i]; L += loc[i]; }
        unsigned inc = L;
#pragma unroll
        for (int o = 1; o < 32; o <<= 1) {
            unsigned t = __shfl_up_sync(0xffffffffu, inc, o);
            if (tid >= o) inc += t;
        }
        unsigned pre = base + inc - L;
        if (pre < KNN && pre + L >= KNN) {
            unsigned cc = pre;
#pragma unroll
            for (int i = 0; i < 8; i++) {
                if (cc < KNN && cc + loc[i] >= KNN)
                    g_thr[row] = (g_b1[row] << 8) | (tid * 8 + i);
                cc += loc[i];
            }
        }
    }
}

// ---------------- H3: gather candidates (MLP-8), exact top-20, sqnn, final ----------------
__global__ void k_h3(int n, const float* __restrict__ T, float* out) {
    extern __shared__ char dsm[];
    float* sv = (float*)dsm;            // [CAP]
    int*   si = (int*)(dsm + 4 * CAP);  // [CAP]
    int row = blockIdx.y, tid = threadIdx.x, lane = tid & 31, w = tid >> 5;
    __shared__ int   s_fi[KNN];
    __shared__ float wv[8]; __shared__ int wi[8], wp[8];
    __shared__ int s_last;

    unsigned thr = g_thr[row];
    const float* v = g_sq + (size_t)row * n;
    for (int base = blockIdx.x * 2048; base < n; base += HGX * 2048) {
        int i0 = base + tid * 8;
        float x[8];
        load8(v, i0, n, x);
#pragma unroll
        for (int j = 0; j < 8; j++) {
            if (i0 + j < n && (fmono(x[j]) >> 16) <= thr) {
                unsigned p = atomicAdd(&g_ccnt[row], 1u);
                if (p < CAP) { g_cv2[row * CAP + p] = x[j]; g_ci2[row * CAP + p] = i0 + j; }
            }
        }
    }
    __threadfence();
    __syncthreads();
    if (tid == 0) s_last = (atomicAdd(&g_d3[row], 1u) == HGX - 1) ? 1 : 0;
    __syncthreads();
    if (!s_last) return;
    if (tid == 0) g_d3[row] = 0;

    int cnt = (int)g_ccnt[row];
    if (cnt > CAP) cnt = CAP;
    for (int j = tid; j < cnt; j += 256) {
        sv[j] = g_cv2[row * CAP + j];
        si[j] = g_ci2[row * CAP + j];
    }
    if (tid == 0) g_ccnt[row] = 0;
    if (tid < 256) { g_hist1[row * 256 + tid] = 0; g_hist2[row * 256 + tid] = 0; }
    __syncthreads();

    for (int it = 0; it < KNN; it++) {
        float bv = FINF; int bi = 0x7fffffff; int bp = -1;
        for (int j = tid; j < cnt; j += 256) {
            float x = sv[j]; int xi = si[j];
            if (x < bv || (x == bv && xi < bi)) { bv = x; bi = xi; bp = j; }
        }
#pragma unroll
        for (int o = 16; o; o >>= 1) {
            float ov = __shfl_xor_sync(0xffffffffu, bv, o);
            int   oi = __shfl_xor_sync(0xffffffffu, bi, o);
            int   op = __shfl_xor_sync(0xffffffffu, bp, o);
            if (ov < bv || (ov == bv && oi < bi)) { bv = ov; bi = oi; bp = op; }
        }
        if (lane == 0) { wv[w] = bv; wi[w] = bi; wp[w] = bp; }
        __syncthreads();
        if (tid == 0) {
            float fv = wv[0]; int fi = wi[0]; int fp = wp[0];
#pragma unroll
            for (int q = 1; q < 8; q++)
                if (wv[q] < fv || (wv[q] == fv && wi[q] < fi)) { fv = wv[q]; fi = wi[q]; fp = wp[q]; }
            s_fi[it] = fi;
            if (fp >= 0) sv[fp] = FINF;
        }
        __syncthreads();
    }

    for (int j = w; j < KNN; j += 8) {
        int rowj = s_fi[j];
        float s = 0.f;
#pragma unroll
        for (int q = 0; q < 4; q++) {
            float4 t  = ((const float4*)(T + (size_t)rowj * D))[lane + 32 * q];
            float4 nb = ((const float4*)g_nb)[row * (D / 4) + lane + 32 * q];
            float a = t.x - nb.x, b = t.y - nb.y, cc = t.z - nb.z, d = t.w - nb.w;
            s += a * a + b * b + cc * cc + d * d;
        }
#pragma unroll
        for (int o = 16; o; o >>= 1) s += __shfl_xor_sync(0xffffffffu, s, o);
        if (lane == 0) g_sqnn[row * KNN + j] = s;
    }
    __threadfence();
    __syncthreads();
    if (tid == 0) s_last = (atomicAdd(&g_done, 1u) == KNN - 1) ? 1 : 0;
    __syncthreads();
    if (s_last) {
        __threadfence();
        if (tid == 0) g_done = 0;
        if (tid < 32) {
            float norm = 0.f, px = 0.f;
            if (tid < KNN) {
                float s = 0.f;
#pragma unroll
                for (int j = 0; j < KNN; j++) s += g_sqnn[tid * KNN + j];
                norm = sqrtf(s / (float)KNN);
                px = g_pxk[tid];
            }
#pragma unroll
            for (int o = 16; o; o >>= 1) {
                norm += __shfl_xor_sync(0xffffffffu, norm, o);
                px   += __shfl_xor_sync(0xffffffffu, px, o);
            }
            if (tid == 0) {
                float pdx = sqrtf(px / (float)KNN);
                float lof = pdx / norm * (float)KNN - 1.f;
                float r = erff(lof * 0.7071067811865476f);
                out[0] = fmaxf(r, 0.f);
            }
        }
    }
}

// ---------------- pass 2: R12-proven smem + ldmatrix HMMA GEMM ----------------
#define SA_BYTES 16384
#define SB_OFF   32768
#define SMEM_P2  65536

static __device__ __forceinline__ void mma16816(float* c, const unsigned* a, const unsigned* b) {
    asm volatile(
        "mma.sync.aligned.m16n8k16.row.col.f32.bf16.bf16.f32 "
        "{%0,%1,%2,%3}, {%4,%5,%6,%7}, {%8,%9}, {%0,%1,%2,%3};"
        : "+f"(c[0]), "+f"(c[1]), "+f"(c[2]), "+f"(c[3])
        : "r"(a[0]), "r"(a[1]), "r"(a[2]), "r"(a[3]), "r"(b[0]), "r"(b[1]));
}
static __device__ __forceinline__ void ldsm4(unsigned* r, unsigned addr) {
    asm volatile("ldmatrix.sync.aligned.m8n8.x4.shared.b16 {%0,%1,%2,%3}, [%4];"
                 : "=r"(r[0]), "=r"(r[1]), "=r"(r[2]), "=r"(r[3]) : "r"(addr));
}

__global__ __launch_bounds__(128) void k_pass2(const float* __restrict__ T, int n) {
    extern __shared__ char sh[];
    unsigned sb = (unsigned)__cvta_generic_to_shared(sh);
    int tid = threadIdx.x, lane = tid & 31, w = tid >> 5;
    int qr = lane >> 2, qc = lane & 3;
    int pbase = blockIdx.x * 128;
    int j8 = lane >> 3, r8 = lane & 7;

#pragma unroll
    for (int i = 0; i < 16; i++) {
        int lin = tid + i * 128;
        int nr = lin >> 6, q = lin & 63;
        uint4 v = *(const uint4*)&g_nbh[nr * 256 + q * 4];
        *(uint4*)(sh + SB_OFF + nr * 1024 + ((q ^ (nr & 7)) << 4)) = v;
    }

    float4 r[16];
#define LDG_A(c)                                                                   \
    {                                                                              \
        _Pragma("unroll")                                                          \
        for (int i = 0; i < 8; i++) {                                              \
            int lc = tid + i * 128;                                                \
            int m = lc >> 3, q = lc & 7;                                           \
            int gp = pbase + m; if (gp >= n) gp = n - 1;                           \
            const float4* s4 = (const float4*)(T + (size_t)gp * D + (c) * 64 + q * 8); \
            r[2 * i]     = __ldg(s4);                                              \
            r[2 * i + 1] = __ldg(s4 + 1);                                          \
        }                                                                          \
    }
#define STS_A(bufp)                                                                \
    {                                                                              \
        _Pragma("unroll")                                                          \
        for (int i = 0; i < 8; i++) {                                              \
            int lc = tid + i * 128;                                                \
            int m = lc >> 3, q = lc & 7;                                           \
            uint4 u;                                                               \
            CVTB(u.x, r[2 * i].x,     r[2 * i].y);                                 \
            CVTB(u.y, r[2 * i].z,     r[2 * i].w);                                 \
            CVTB(u.z, r[2 * i + 1].x, r[2 * i + 1].y);                             \
            CVTB(u.w, r[2 * i + 1].z, r[2 * i + 1].w);                             \
            *(uint4*)((bufp) + m * 128 + ((q ^ (m & 7)) << 4)) = u;                \
        }                                                                          \
    }

    LDG_A(0);
    STS_A(sh);
    LDG_A(1);
    __syncthreads();

    float acc[2][4][4];
#pragma unroll
    for (int mt = 0; mt < 2; mt++)
#pragma unroll
        for (int nt = 0; nt < 4; nt++)
#pragma unroll
            for (int q = 0; q < 4; q++) acc[mt][nt][q] = 0.f;

#pragma unroll 1
    for (int c = 0; c < 8; c++) {
        unsigned bufA = sb + (c & 1) * SA_BYTES;
#pragma unroll
        for (int s = 0; s < 4; s++) {
            unsigned af[2][4], bf[2][4];
#pragma unroll
            for (int mt = 0; mt < 2; mt++) {
                int m = w * 32 + mt * 16 + ((j8 & 1) << 3) + r8;
                int q = s * 2 + (j8 >> 1);
                ldsm4(af[mt], bufA + m * 128 + ((q ^ (m & 7)) << 4));
            }
#pragma unroll
            for (int np = 0; np < 2; np++) {
                int nr = np * 16 + ((j8 >> 1) << 3) + r8;
                int q = (c * 4 + s) * 2 + (j8 & 1);
                ldsm4(bf[np], sb + SB_OFF + nr * 1024 + ((q ^ (nr & 7)) << 4));
            }
#pragma unroll
            for (int mt = 0; mt < 2; mt++)
#pragma unroll
                for (int np = 0; np < 2; np++) {
                    mma16816(acc[mt][2 * np],     af[mt], &bf[np][0]);
                    mma16816(acc[mt][2 * np + 1], af[mt], &bf[np][2]);
                }
        }
        if (c + 1 < 8) STS_A(sh + ((c + 1) & 1) * SA_BYTES);
        if (c + 2 < 8) LDG_A(c + 2);
        __syncthreads();
    }

#pragma unroll
    for (int mt = 0; mt < 2; mt++) {
        int p0 = pbase + w * 32 + mt * 16 + qr;
        int p1 = p0 + 8;
        float tn0 = (p0 < n) ? g_tn2[p0] : 0.f;
        float tn1 = (p1 < n) ? g_tn2[p1] : 0.f;
#pragma unroll
        for (int nt = 0; nt < 4; nt++) {
            int k0 = nt * 8 + qc * 2;
            if (k0 < KNN) {
                if (p0 < n) g_sq[(size_t)k0 * n + p0] = tn0 - 2.f * acc[mt][nt][0];
                if (p1 < n) g_sq[(size_t)k0 * n + p1] = tn1 - 2.f * acc[mt][nt][2];
            }
            if (k0 + 1 < KNN) {
                if (p0 < n) g_sq[(size_t)(k0 + 1) * n + p0] = tn0 - 2.f * acc[mt][nt][1];
                if (p1 < n) g_sq[(size_t)(k0 + 1) * n + p1] = tn1 - 2.f * acc[mt][nt][3];
            }
        }
    }
}

// ---------------- launch: 6 nodes ----------------
extern "C" void kernel_launch(void* const* d_in, const int* in_sizes, int n_in,
                              void* d_out, int out_size) {
    const float* A = (const float*)d_in[0];
    const float* B = (const float*)d_in[1];
    const float *X, *T;
    int n;
    if (in_sizes[0] == D) { X = A; T = B; n = in_sizes[1] / D; }
    else                  { X = B; T = A; n = in_sizes[0] / D; }
    if (n > MAXN) n = MAXN;

    int nch = (n + CHUNK - 1) / CHUNK;
    int nbx = (nch + 7) / 8;

    cudaFuncSetAttribute(k_pass2, cudaFuncAttributeMaxDynamicSharedMemorySize, SMEM_P2);
    cudaFuncSetAttribute(k_h3, cudaFuncAttributeMaxDynamicSharedMemorySize, CAP * 8);

    k_pass1<<<(n + 7) / 8, 256>>>(X, T, n);
    k_topk0<<<nbx, 256>>>(n, nch, X, T);
    k_pass2<<<(n + 127) / 128, 128, SMEM_P2>>>(T, n);
    k_h1<<<dim3(HGX, KNN), 256>>>(n);
    k_h2<<<dim3(HGX, KNN), 256>>>(n);
    k_h3<<<dim3(HGX, KNN), 256, CAP * 8>>>(n, T, (float*)d_out);
}